// round 2
// baseline (speedup 1.0000x reference)
#include <cuda_runtime.h>
#include <cstdint>

#define B_ 8
#define N_ 2048
#define F_ 64
#define HID_ 32
#define BN_TOTAL (B_*N_)

// ---------------- scratch (static device globals; no allocation) ----------------
__device__ float g_dm[BN_TOTAL];          // D^{-1/2} per (b,node)
__device__ float g_add[BN_TOTAL];         // self-loop add indicator (0 or 1)
__device__ float g_Y[BN_TOTAL*HID_];      // Y = dm .* (H @ W)
__device__ float g_H[BN_TOTAL*HID_];      // layer output
__device__ float g_pool[B_*HID_];         // global max pool

// ---------------- helpers ----------------
__device__ __forceinline__ float2 ffma2(float2 a, float2 b, float2 c) {
    float2 d;
    asm("fma.rn.f32x2 %0, %1, %2, %3;"
        : "=l"(*(unsigned long long*)&d)
        : "l"(*(unsigned long long*)&a),
          "l"(*(unsigned long long*)&b),
          "l"(*(unsigned long long*)&c));
    return d;
}

__device__ __forceinline__ void cp16(float* dst, const float* src) {
    uint32_t s = (uint32_t)__cvta_generic_to_shared(dst);
    asm volatile("cp.async.cg.shared.global [%0], [%1], 16;" :: "r"(s), "l"(src));
}

// ---------------- degree + normalization factors ----------------
// one warp per row of A; 8 warps per block
__global__ void deg_kernel(const float* __restrict__ a) {
    int row  = blockIdx.x * 8 + (threadIdx.x >> 5);
    int lane = threadIdx.x & 31;
    const float4* ar4 = (const float4*)(a + (size_t)row * N_);
    float s = 0.f;
    #pragma unroll
    for (int j = 0; j < N_/128; j++) {
        float4 v = ar4[lane + j*32];
        s += (v.x + v.y) + (v.z + v.w);
    }
    #pragma unroll
    for (int o = 16; o; o >>= 1) s += __shfl_xor_sync(0xffffffffu, s, o);
    if (lane == 0) {
        int i = row & (N_ - 1);
        float diag = a[(size_t)row * N_ + i];
        float add  = (fabsf(diag) < 1e-7f) ? 1.0f : 0.0f;
        g_add[row] = add;
        g_dm[row]  = 1.0f / sqrtf(s + add);
    }
}

// ---------------- Y = dm .* (Hin @ W)  (small GEMM) ----------------
// 8 rows per block; thread (r,f): r=t/32, f=t%32
template<int K>
__global__ void y_kernel(const float* __restrict__ Hin, const float* __restrict__ W) {
    __shared__ float Ws[K*HID_];
    __shared__ float Hs[8][K];
    const float* src = (K == F_) ? Hin : (const float*)g_H;
    int t = threadIdx.x;
    int row0 = blockIdx.x * 8;
    for (int i = t; i < K*HID_; i += 256) Ws[i] = W[i];
    for (int i = t; i < 8*K;   i += 256) Hs[i/K][i%K] = src[(size_t)row0*K + i];
    __syncthreads();
    int r = t >> 5, f = t & 31;
    float acc = 0.f;
    #pragma unroll
    for (int k = 0; k < K; k++) acc += Hs[r][k] * Ws[k*HID_ + f];
    int row = row0 + r;
    g_Y[(size_t)row*HID_ + f] = g_dm[row] * acc;
}

// ---------------- big GEMM: H = relu(dm_i*(A@Y + add_i*Y_i) + bias) ----------------
#define BM 128
#define BK 32
#define NT (N_/BK)
#define AS_STR 36   // padded row stride (floats), keeps 16B alignment, 2-way max conflicts
#define YT_STR 36

__global__ void __launch_bounds__(256) gemm_kernel(const float* __restrict__ A,
                                                   const float* __restrict__ bias) {
    __shared__ float As[2][BM*AS_STR];      // A tile, row-major [r][k]
    __shared__ float Yt[2][HID_*YT_STR];    // Y tile, transposed [f][k]
    int t = threadIdx.x;
    int b = blockIdx.y;
    int row0 = blockIdx.x * BM;
    const float* Ab = A   + (size_t)b * N_ * N_;
    const float* Yg = g_Y + (size_t)b * N_ * HID_;

    int yk = t >> 3, yf = (t & 7) * 4;      // this thread's Y float4: (k=yk, f=yf..yf+3)
    int rbase = (t >> 3) * 4;               // 4 rows
    int cbase = (t & 7) * 4;                // 4 cols

    float4 yreg;

    float2 acc[4][4];
    #pragma unroll
    for (int r = 0; r < 4; r++)
        #pragma unroll
        for (int c = 0; c < 4; c++) acc[r][c] = make_float2(0.f, 0.f);

    // ---- prologue: tile 0 ----
    #pragma unroll
    for (int i = 0; i < 4; i++) {
        int li = i*256 + t;
        int r = li >> 3, kk = (li & 7) * 4;
        cp16(&As[0][r*AS_STR + kk], &Ab[(size_t)(row0 + r)*N_ + kk]);
    }
    asm volatile("cp.async.commit_group;");
    yreg = *(const float4*)&Yg[yk*HID_ + yf];
    Yt[0][(yf+0)*YT_STR + yk] = yreg.x;
    Yt[0][(yf+1)*YT_STR + yk] = yreg.y;
    Yt[0][(yf+2)*YT_STR + yk] = yreg.z;
    Yt[0][(yf+3)*YT_STR + yk] = yreg.w;
    asm volatile("cp.async.wait_group 0;" ::: "memory");
    __syncthreads();

    for (int kt = 0; kt < NT; kt++) {
        int s = kt & 1;
        if (kt + 1 < NT) {
            int k0 = (kt + 1) * BK;
            #pragma unroll
            for (int i = 0; i < 4; i++) {
                int li = i*256 + t;
                int r = li >> 3, kk = (li & 7) * 4;
                cp16(&As[s^1][r*AS_STR + kk], &Ab[(size_t)(row0 + r)*N_ + k0 + kk]);
            }
            asm volatile("cp.async.commit_group;");
            yreg = *(const float4*)&Yg[(k0 + yk)*HID_ + yf];
        }
        // ---- compute on stage s ----
        #pragma unroll
        for (int kk = 0; kk < BK; kk += 4) {
            float4 av[4], yv[4];
            #pragma unroll
            for (int r = 0; r < 4; r++)
                av[r] = *(const float4*)&As[s][(rbase + r)*AS_STR + kk];
            #pragma unroll
            for (int c = 0; c < 4; c++)
                yv[c] = *(const float4*)&Yt[s][(cbase + c)*YT_STR + kk];
            #pragma unroll
            for (int r = 0; r < 4; r++)
                #pragma unroll
                for (int c = 0; c < 4; c++) {
                    acc[r][c] = ffma2(make_float2(av[r].x, av[r].y),
                                      make_float2(yv[c].x, yv[c].y), acc[r][c]);
                    acc[r][c] = ffma2(make_float2(av[r].z, av[r].w),
                                      make_float2(yv[c].z, yv[c].w), acc[r][c]);
                }
        }
        if (kt + 1 < NT) {
            asm volatile("cp.async.wait_group 0;" ::: "memory");
            __syncthreads();                       // compute(s) done; As[s^1] landed
            Yt[s^1][(yf+0)*YT_STR + yk] = yreg.x;  // safe: Yt[s^1] no longer read
            Yt[s^1][(yf+1)*YT_STR + yk] = yreg.y;
            Yt[s^1][(yf+2)*YT_STR + yk] = yreg.z;
            Yt[s^1][(yf+3)*YT_STR + yk] = yreg.w;
            __syncthreads();
        }
    }

    // ---- epilogue: self-loop + dm scale + bias + relu ----
    #pragma unroll
    for (int r = 0; r < 4; r++) {
        int row = row0 + rbase + r;
        float dmv = g_dm[b*N_ + row];
        float ad  = g_add[b*N_ + row];
        #pragma unroll
        for (int c = 0; c < 4; c++) {
            int col = cbase + c;
            float v = acc[r][c].x + acc[r][c].y;
            if (ad != 0.f) v += ad * Yg[(size_t)row*HID_ + col];
            v = dmv * v + bias[col];
            g_H[((size_t)b*N_ + row)*HID_ + col] = fmaxf(v, 0.f);
        }
    }
}

// ---------------- global max pool ----------------
__global__ void pool_kernel() {
    int b = blockIdx.x, t = threadIdx.x;
    int f = t & 31, g = t >> 5;
    float m = -1e30f;
    for (int n = g; n < N_; n += 8)
        m = fmaxf(m, g_H[((size_t)b*N_ + n)*HID_ + f]);
    __shared__ float red[256];
    red[t] = m; __syncthreads();
    if (t < 128) red[t] = fmaxf(red[t], red[t+128]); __syncthreads();
    if (t < 64)  red[t] = fmaxf(red[t], red[t+64]);  __syncthreads();
    if (t < 32)  g_pool[b*HID_ + t] = fmaxf(red[t], red[t+32]);
}

// ---------------- MLP head: out = relu(g@Wf1+bf1)@Wf2+bf2 ----------------
__global__ void head_kernel(const float* __restrict__ Wf1, const float* __restrict__ bf1,
                            const float* __restrict__ Wf2, const float* __restrict__ bf2,
                            float* __restrict__ out) {
    int w = threadIdx.x >> 5, lane = threadIdx.x & 31;
    float o = 0.f;
    #pragma unroll
    for (int ii = 0; ii < 2; ii++) {
        int j = lane + 32*ii;
        float s = bf1[j];
        #pragma unroll
        for (int f = 0; f < HID_; f++) s += g_pool[w*HID_ + f] * Wf1[f*2*HID_ + j];
        o += fmaxf(s, 0.f) * Wf2[j];
    }
    #pragma unroll
    for (int off = 16; off; off >>= 1) o += __shfl_xor_sync(0xffffffffu, o, off);
    if (lane == 0) out[w] = o + bf2[0];
}

// ---------------- launch ----------------
extern "C" void kernel_launch(void* const* d_in, const int* in_sizes, int n_in,
                              void* d_out, int out_size) {
    const float* x   = (const float*)d_in[0];
    const float* a   = (const float*)d_in[1];
    const float* W1  = (const float*)d_in[2];
    const float* b1  = (const float*)d_in[3];
    const float* W2  = (const float*)d_in[4];
    const float* b2  = (const float*)d_in[5];
    const float* W3  = (const float*)d_in[6];
    const float* b3  = (const float*)d_in[7];
    const float* Wf1 = (const float*)d_in[8];
    const float* bf1 = (const float*)d_in[9];
    const float* Wf2 = (const float*)d_in[10];
    const float* bf2 = (const float*)d_in[11];
    float* out = (float*)d_out;

    dim3 gg(N_/BM, B_);

    deg_kernel<<<BN_TOTAL/8, 256>>>(a);

    y_kernel<F_><<<BN_TOTAL/8, 256>>>(x, W1);
    gemm_kernel<<<gg, 256>>>(a, b1);

    y_kernel<HID_><<<BN_TOTAL/8, 256>>>(nullptr, W2);
    gemm_kernel<<<gg, 256>>>(a, b2);

    y_kernel<HID_><<<BN_TOTAL/8, 256>>>(nullptr, W3);
    gemm_kernel<<<gg, 256>>>(a, b3);

    pool_kernel<<<B_, 256>>>();
    head_kernel<<<1, 256>>>(Wf1, bf1, Wf2, bf2, out);
}

// round 5
// speedup vs baseline: 2.1756x; 2.1756x over previous
#include <cuda_runtime.h>
#include <cuda_bf16.h>
#include <cstdint>

#define B_ 8
#define N_ 2048
#define F_ 64
#define HID_ 32
#define BN_TOTAL (B_*N_)

// ---------------- scratch ----------------
__device__ float g_dm[BN_TOTAL];
__device__ float g_add[BN_TOTAL];
__device__ float g_Y[BN_TOTAL*HID_];                 // fp32 Y (self-loop epilogue)
__device__ float g_H[BN_TOTAL*HID_];
__device__ float g_pool[B_*HID_];
__device__ __nv_bfloat16 g_YThi[B_*HID_*N_];         // Y^T bf16 hi  [b][f][n]
__device__ __nv_bfloat16 g_YTlo[B_*HID_*N_];         // Y^T bf16 lo

// ---------------- mma helper (baseline sm_80+ PTX; works on sm_103 non-a) ----------------
__device__ __forceinline__ void mma16816(float* c, const uint32_t* a, const uint32_t* b) {
    asm volatile("mma.sync.aligned.m16n8k16.row.col.f32.bf16.bf16.f32 "
        "{%0,%1,%2,%3}, {%4,%5,%6,%7}, {%8,%9}, {%0,%1,%2,%3};"
        : "+f"(c[0]), "+f"(c[1]), "+f"(c[2]), "+f"(c[3])
        : "r"(a[0]), "r"(a[1]), "r"(a[2]), "r"(a[3]), "r"(b[0]), "r"(b[1]));
}
__device__ __forceinline__ unsigned short bf16u(__nv_bfloat16 h) {
    return *(unsigned short*)&h;
}

// ---------------- degree + normalization ----------------
__global__ void deg_kernel(const float* __restrict__ a) {
    int row  = blockIdx.x * 8 + (threadIdx.x >> 5);
    int lane = threadIdx.x & 31;
    const float4* ar4 = (const float4*)(a + (size_t)row * N_);
    float s = 0.f;
    #pragma unroll
    for (int j = 0; j < N_/128; j++) {
        float4 v = ar4[lane + j*32];
        s += (v.x + v.y) + (v.z + v.w);
    }
    #pragma unroll
    for (int o = 16; o; o >>= 1) s += __shfl_xor_sync(0xffffffffu, s, o);
    if (lane == 0) {
        int i = row & (N_ - 1);
        float diag = a[(size_t)row * N_ + i];
        float add  = (fabsf(diag) < 1e-7f) ? 1.0f : 0.0f;
        g_add[row] = add;
        g_dm[row]  = 1.0f / sqrtf(s + add);
    }
}

// ---------------- Y = dm .* (Hin @ W); emits fp32 + split-bf16 transposed ----------------
template<int K>
__global__ void y_kernel(const float* __restrict__ Hin, const float* __restrict__ W) {
    __shared__ float Ws[K*HID_];
    __shared__ float Hs[32][K];
    const float* src = (K == F_) ? Hin : (const float*)g_H;
    int t = threadIdx.x;
    int row0 = blockIdx.x * 32;
    for (int i = t; i < K*HID_; i += 256) Ws[i] = W[i];
    for (int i = t; i < 32*K;  i += 256) Hs[i/K][i%K] = src[(size_t)row0*K + i];
    __syncthreads();
    int rb = (t >> 5) * 4, f = t & 31;
    float acc[4] = {0.f, 0.f, 0.f, 0.f};
    #pragma unroll
    for (int k = 0; k < K; k++) {
        float wv = Ws[k*HID_ + f];
        acc[0] += Hs[rb+0][k] * wv;
        acc[1] += Hs[rb+1][k] * wv;
        acc[2] += Hs[rb+2][k] * wv;
        acc[3] += Hs[rb+3][k] * wv;
    }
    #pragma unroll
    for (int j = 0; j < 4; j++) {
        int row = row0 + rb + j;
        float v = g_dm[row] * acc[j];
        g_Y[(size_t)row*HID_ + f] = v;
        int bb = row >> 11, n = row & (N_ - 1);
        __nv_bfloat16 hb = __float2bfloat16(v);
        float l = v - __bfloat162float(hb);
        size_t ti = ((size_t)bb*HID_ + f)*N_ + n;
        g_YThi[ti] = hb;
        g_YTlo[ti] = __float2bfloat16(l);
    }
}

// ---------------- HMMA GEMM: H = relu(dm_i*(A@Y + add_i*Y_i) + bias) ----------------
#define BM 64
#define BK 32
#define NT (N_/BK)
// per-stage smem block: AHI(64x40 bf16=5120B) | ALO(5120) | BHI(32x40=2560) | BLO(2560)
#define STG 15360
#define A_ROWB 80   // padded row pitch in bytes (40 bf16)

__global__ void __launch_bounds__(256) gemm_kernel(const float* __restrict__ A,
                                                   const float* __restrict__ bias) {
    __shared__ char sm[2*STG];
    int t = threadIdx.x;
    int lane = t & 31, w = t >> 5;
    int wm = w & 3, wn = w >> 2;               // warp tile: rows wm*16, cols wn*16
    int g = lane >> 2, t4 = lane & 3;
    int b = blockIdx.y, row0 = blockIdx.x * BM;
    const float* Ab = A + (size_t)b*N_*N_;
    const __nv_bfloat16* BTh = g_YThi + (size_t)b*HID_*N_;
    const __nv_bfloat16* BTl = g_YTlo + (size_t)b*HID_*N_;

    // fill mapping: A: thread -> (row fr, 8 cols at fq*8); B: 8 k-elems per thread
    int fr = t >> 2, fq = t & 3;
    int bn = (t & 127) >> 2, bseg = t & 3;
    const __nv_bfloat16* BTsrc = ((t < 128) ? BTh : BTl) + (size_t)bn*N_ + bseg*8;
    int bsmoff = ((t < 128) ? 10240 : 12800) + bn*A_ROWB + bseg*16;

    float4 va0, va1; uint4 vbv;
    float acc[2][4];
    #pragma unroll
    for (int c = 0; c < 2; c++)
        #pragma unroll
        for (int i = 0; i < 4; i++) acc[c][i] = 0.f;

    // ---- prologue: load tile 0 ----
    {
        const float4* p = (const float4*)(Ab + (size_t)(row0 + fr)*N_ + fq*8);
        va0 = p[0]; va1 = p[1];
        vbv = *(const uint4*)(BTsrc);
    }

    for (int kt = 0; kt < NT; kt++) {
        int s = kt & 1;
        // convert + store current regs into stage s
        {
            float f[8] = {va0.x,va0.y,va0.z,va0.w,va1.x,va1.y,va1.z,va1.w};
            uint32_t hs[8], ls[8];
            #pragma unroll
            for (int i = 0; i < 8; i++) {
                __nv_bfloat16 h = __float2bfloat16(f[i]);
                float l = f[i] - __bfloat162float(h);
                hs[i] = bf16u(h);
                ls[i] = bf16u(__float2bfloat16(l));
            }
            uint4 hv = make_uint4(hs[0]|(hs[1]<<16), hs[2]|(hs[3]<<16),
                                  hs[4]|(hs[5]<<16), hs[6]|(hs[7]<<16));
            uint4 lv = make_uint4(ls[0]|(ls[1]<<16), ls[2]|(ls[3]<<16),
                                  ls[4]|(ls[5]<<16), ls[6]|(ls[7]<<16));
            *(uint4*)(sm + s*STG + fr*A_ROWB + fq*16)        = hv;
            *(uint4*)(sm + s*STG + 5120 + fr*A_ROWB + fq*16) = lv;
            *(uint4*)(sm + s*STG + bsmoff)                   = vbv;
        }
        __syncthreads();
        // prefetch next tile into regs (overlaps with compute below)
        if (kt + 1 < NT) {
            int k0 = (kt + 1) * BK;
            const float4* p = (const float4*)(Ab + (size_t)(row0 + fr)*N_ + k0 + fq*8);
            va0 = p[0]; va1 = p[1];
            vbv = *(const uint4*)(BTsrc + k0);
        }
        // ---- compute on stage s ----
        char* base = sm + s*STG;
        #pragma unroll
        for (int kk = 0; kk < 2; kk++) {
            int kb = kk * 32;                          // 16 k-elems = 32 bytes
            uint32_t ah[4], al[4];
            char* arow = base + (wm*16 + g)*A_ROWB + t4*4 + kb;
            ah[0] = *(uint32_t*)(arow);
            ah[1] = *(uint32_t*)(arow + 8*A_ROWB);
            ah[2] = *(uint32_t*)(arow + 16);
            ah[3] = *(uint32_t*)(arow + 8*A_ROWB + 16);
            char* arl = arow + 5120;
            al[0] = *(uint32_t*)(arl);
            al[1] = *(uint32_t*)(arl + 8*A_ROWB);
            al[2] = *(uint32_t*)(arl + 16);
            al[3] = *(uint32_t*)(arl + 8*A_ROWB + 16);
            #pragma unroll
            for (int c = 0; c < 2; c++) {
                uint32_t bh[2], bl[2];
                char* brow = base + 10240 + (wn*16 + c*8 + g)*A_ROWB + t4*4 + kb;
                bh[0] = *(uint32_t*)(brow);
                bh[1] = *(uint32_t*)(brow + 16);
                bl[0] = *(uint32_t*)(brow + 2560);
                bl[1] = *(uint32_t*)(brow + 2560 + 16);
                mma16816(acc[c], ah, bh);
                mma16816(acc[c], ah, bl);
                mma16816(acc[c], al, bh);
            }
        }
        __syncthreads();
    }

    // ---- epilogue: self-loop + dm + bias + relu ----
    int rowL = row0 + wm*16 + g;
    int rowH = rowL + 8;
    float dmL = g_dm[b*N_ + rowL], adL = g_add[b*N_ + rowL];
    float dmH = g_dm[b*N_ + rowH], adH = g_add[b*N_ + rowH];
    const float* Yg = g_Y + (size_t)b*N_*HID_;
    float* Hg = g_H + (size_t)b*N_*HID_;
    #pragma unroll
    for (int c = 0; c < 2; c++) {
        int col = wn*16 + c*8 + 2*t4;
        float2 bs = *(const float2*)&bias[col];
        float2 yL = *(const float2*)&Yg[(size_t)rowL*HID_ + col];
        float2 yH = *(const float2*)&Yg[(size_t)rowH*HID_ + col];
        float2 o;
        o.x = fmaxf(fmaf(dmL, acc[c][0] + adL*yL.x, bs.x), 0.f);
        o.y = fmaxf(fmaf(dmL, acc[c][1] + adL*yL.y, bs.y), 0.f);
        *(float2*)&Hg[(size_t)rowL*HID_ + col] = o;
        o.x = fmaxf(fmaf(dmH, acc[c][2] + adH*yH.x, bs.x), 0.f);
        o.y = fmaxf(fmaf(dmH, acc[c][3] + adH*yH.y, bs.y), 0.f);
        *(float2*)&Hg[(size_t)rowH*HID_ + col] = o;
    }
}

// ---------------- global max pool ----------------
__global__ void pool_kernel() {
    int b = blockIdx.x, t = threadIdx.x;
    int f = t & 31, g = t >> 5;
    float m = -1e30f;
    for (int n = g; n < N_; n += 8)
        m = fmaxf(m, g_H[((size_t)b*N_ + n)*HID_ + f]);
    __shared__ float red[256];
    red[t] = m; __syncthreads();
    if (t < 128) red[t] = fmaxf(red[t], red[t+128]); __syncthreads();
    if (t < 64)  red[t] = fmaxf(red[t], red[t+64]);  __syncthreads();
    if (t < 32)  g_pool[b*HID_ + t] = fmaxf(red[t], red[t+32]);
}

// ---------------- MLP head ----------------
__global__ void head_kernel(const float* __restrict__ Wf1, const float* __restrict__ bf1,
                            const float* __restrict__ Wf2, const float* __restrict__ bf2,
                            float* __restrict__ out) {
    int w = threadIdx.x >> 5, lane = threadIdx.x & 31;
    float o = 0.f;
    #pragma unroll
    for (int ii = 0; ii < 2; ii++) {
        int j = lane + 32*ii;
        float s = bf1[j];
        #pragma unroll
        for (int f = 0; f < HID_; f++) s += g_pool[w*HID_ + f] * Wf1[f*2*HID_ + j];
        o += fmaxf(s, 0.f) * Wf2[j];
    }
    #pragma unroll
    for (int off = 16; off; off >>= 1) o += __shfl_xor_sync(0xffffffffu, o, off);
    if (lane == 0) out[w] = o + bf2[0];
}

// ---------------- launch ----------------
extern "C" void kernel_launch(void* const* d_in, const int* in_sizes, int n_in,
                              void* d_out, int out_size) {
    const float* x   = (const float*)d_in[0];
    const float* a   = (const float*)d_in[1];
    const float* W1  = (const float*)d_in[2];
    const float* b1  = (const float*)d_in[3];
    const float* W2  = (const float*)d_in[4];
    const float* b2  = (const float*)d_in[5];
    const float* W3  = (const float*)d_in[6];
    const float* b3  = (const float*)d_in[7];
    const float* Wf1 = (const float*)d_in[8];
    const float* bf1 = (const float*)d_in[9];
    const float* Wf2 = (const float*)d_in[10];
    const float* bf2 = (const float*)d_in[11];
    float* out = (float*)d_out;

    dim3 gg(N_/BM, B_);

    deg_kernel<<<BN_TOTAL/8, 256>>>(a);

    y_kernel<F_><<<BN_TOTAL/32, 256>>>(x, W1);
    gemm_kernel<<<gg, 256>>>(a, b1);

    y_kernel<HID_><<<BN_TOTAL/32, 256>>>(nullptr, W2);
    gemm_kernel<<<gg, 256>>>(a, b2);

    y_kernel<HID_><<<BN_TOTAL/32, 256>>>(nullptr, W3);
    gemm_kernel<<<gg, 256>>>(a, b3);

    pool_kernel<<<B_, 256>>>();
    head_kernel<<<1, 256>>>(Wf1, bf1, Wf2, bf2, out);
}

// round 6
// speedup vs baseline: 3.4268x; 1.5751x over previous
#include <cuda_runtime.h>
#include <cuda_bf16.h>
#include <cstdint>

#define B_ 8
#define N_ 2048
#define F_ 64
#define HID_ 32
#define BN_TOTAL (B_*N_)

// ---------------- scratch ----------------
__device__ float g_dm[BN_TOTAL];
__device__ float g_add[BN_TOTAL];
__device__ float g_Y[BN_TOTAL*HID_];                 // fp32 Y (self-loop epilogue)
__device__ float g_H[BN_TOTAL*HID_];
__device__ float g_pool[B_*HID_];
__device__ __nv_bfloat16 g_YThi[B_*HID_*N_];         // Y^T bf16 hi  [b][f][n]
__device__ __nv_bfloat16 g_YTlo[B_*HID_*N_];         // Y^T bf16 lo
__device__ __nv_bfloat16 g_Ahi[(size_t)BN_TOTAL*N_]; // A bf16 hi  [b][n][k]
__device__ __nv_bfloat16 g_Alo[(size_t)BN_TOTAL*N_]; // A bf16 lo

// ---------------- helpers ----------------
__device__ __forceinline__ void mma16816(float* c, const uint32_t* a, const uint32_t* b) {
    asm volatile("mma.sync.aligned.m16n8k16.row.col.f32.bf16.bf16.f32 "
        "{%0,%1,%2,%3}, {%4,%5,%6,%7}, {%8,%9}, {%0,%1,%2,%3};"
        : "+f"(c[0]), "+f"(c[1]), "+f"(c[2]), "+f"(c[3])
        : "r"(a[0]), "r"(a[1]), "r"(a[2]), "r"(a[3]), "r"(b[0]), "r"(b[1]));
}
__device__ __forceinline__ unsigned short bf16u(__nv_bfloat16 h) { return *(unsigned short*)&h; }
__device__ __forceinline__ void cp16(void* dst, const void* src) {
    uint32_t s = (uint32_t)__cvta_generic_to_shared(dst);
    asm volatile("cp.async.cg.shared.global [%0], [%1], 16;" :: "r"(s), "l"(src));
}

// ---------------- degree + normalization + bf16 hi/lo split of A ----------------
__global__ void deg_cvt_kernel(const float* __restrict__ a) {
    int row  = blockIdx.x * 8 + (threadIdx.x >> 5);   // global row in [0, 16384)
    int lane = threadIdx.x & 31;
    const float4* ar4 = (const float4*)(a + (size_t)row * N_);
    __nv_bfloat16* hrow = g_Ahi + (size_t)row * N_;
    __nv_bfloat16* lrow = g_Alo + (size_t)row * N_;
    float s = 0.f;
    #pragma unroll
    for (int j = 0; j < N_/128; j++) {
        float4 v = ar4[lane + j*32];
        s += (v.x + v.y) + (v.z + v.w);
        float f[4] = {v.x, v.y, v.z, v.w};
        uint32_t hs[4], ls[4];
        #pragma unroll
        for (int i = 0; i < 4; i++) {
            __nv_bfloat16 h = __float2bfloat16(f[i]);
            hs[i] = bf16u(h);
            ls[i] = bf16u(__float2bfloat16(f[i] - __bfloat162float(h)));
        }
        uint2 hv = make_uint2(hs[0]|(hs[1]<<16), hs[2]|(hs[3]<<16));
        uint2 lv = make_uint2(ls[0]|(ls[1]<<16), ls[2]|(ls[3]<<16));
        *(uint2*)(hrow + (size_t)(lane + j*32)*4) = hv;
        *(uint2*)(lrow + (size_t)(lane + j*32)*4) = lv;
    }
    #pragma unroll
    for (int o = 16; o; o >>= 1) s += __shfl_xor_sync(0xffffffffu, s, o);
    if (lane == 0) {
        int i = row & (N_ - 1);
        float diag = a[(size_t)row * N_ + i];
        float add  = (fabsf(diag) < 1e-7f) ? 1.0f : 0.0f;
        g_add[row] = add;
        g_dm[row]  = 1.0f / sqrtf(s + add);
    }
}

// ---------------- Y = dm .* (Hin @ W); fp32 + split-bf16 transposed via smem ----------------
template<int K>
__global__ void y_kernel(const float* __restrict__ Hin, const float* __restrict__ W) {
    __shared__ float Ws[K*HID_];
    __shared__ float Hs[32][K];
    __shared__ float Ysm[32][33];
    const float* src = (K == F_) ? Hin : (const float*)g_H;
    int t = threadIdx.x;
    int row0 = blockIdx.x * 32;
    for (int i = t; i < K*HID_/4; i += 256) ((float4*)Ws)[i] = ((const float4*)W)[i];
    for (int i = t; i < 32*K/4;  i += 256) ((float4*)Hs)[i] = ((const float4*)(src + (size_t)row0*K))[i];
    __syncthreads();
    int rb = (t >> 5) * 4, f = t & 31;
    float acc[4] = {0.f, 0.f, 0.f, 0.f};
    #pragma unroll
    for (int k = 0; k < K; k++) {
        float wv = Ws[k*HID_ + f];
        acc[0] += Hs[rb+0][k] * wv;
        acc[1] += Hs[rb+1][k] * wv;
        acc[2] += Hs[rb+2][k] * wv;
        acc[3] += Hs[rb+3][k] * wv;
    }
    #pragma unroll
    for (int j = 0; j < 4; j++) {
        int row = row0 + rb + j;
        float v = g_dm[row] * acc[j];
        g_Y[(size_t)row*HID_ + f] = v;
        Ysm[rb + j][f] = v;
    }
    __syncthreads();
    // transposed split write: warp w handles 4 feature rows, lane = node
    int w = t >> 5, lane = t & 31;
    int bb = row0 >> 11, n0 = row0 & (N_ - 1);
    #pragma unroll
    for (int jj = 0; jj < 4; jj++) {
        int ff = w*4 + jj;
        float v = Ysm[lane][ff];
        __nv_bfloat16 h = __float2bfloat16(v);
        size_t ti = ((size_t)bb*HID_ + ff)*N_ + n0 + lane;
        g_YThi[ti] = h;
        g_YTlo[ti] = __float2bfloat16(v - __bfloat162float(h));
    }
}

// ---------------- HMMA GEMM (pure cp.async pipeline) ----------------
#define BM 64
#define BK 64
#define NT (N_/BK)
#define NSTAGE 3
#define AHI_OFF 0
#define ALO_OFF 8192
#define BHI_OFF 16384
#define BLO_OFF 20480
#define STGSZ   24576
#define GEMM_SMEM (NSTAGE*STGSZ)

__device__ __forceinline__ void fill_async(char* stage, int t, int b, int row0, int k0) {
    const __nv_bfloat16* Ah = g_Ahi + ((size_t)(b*N_ + row0))*N_ + k0;
    const __nv_bfloat16* Al = g_Alo + ((size_t)(b*N_ + row0))*N_ + k0;
    const __nv_bfloat16* Bh = g_YThi + (size_t)b*HID_*N_ + k0;
    const __nv_bfloat16* Bl = g_YTlo + (size_t)b*HID_*N_ + k0;
    // A: 64 rows x 128B = 512 chunks each of hi/lo
    #pragma unroll
    for (int i = 0; i < 2; i++) {
        int c = t + i*256;
        int r = c >> 3, seg = c & 7;
        int x = (seg*16) ^ ((r & 7) << 4);
        cp16(stage + AHI_OFF + r*128 + x, Ah + (size_t)r*N_ + seg*8);
        cp16(stage + ALO_OFF + r*128 + x, Al + (size_t)r*N_ + seg*8);
    }
    // B: 32 rows x 128B = 256 chunks each of hi/lo
    {
        int r = t >> 3, seg = t & 7;
        int x = (seg*16) ^ ((r & 7) << 4);
        cp16(stage + BHI_OFF + r*128 + x, Bh + (size_t)r*N_ + seg*8);
        cp16(stage + BLO_OFF + r*128 + x, Bl + (size_t)r*N_ + seg*8);
    }
}

__global__ void __launch_bounds__(256) gemm_kernel(const float* __restrict__ bias) {
    extern __shared__ char sm[];
    int t = threadIdx.x;
    int lane = t & 31, w = t >> 5;
    int wm = w & 3, wn = w >> 2;
    int g = lane >> 2, t4 = lane & 3;
    int b = blockIdx.y, row0 = blockIdx.x * BM;

    float acc[2][4];
    #pragma unroll
    for (int c = 0; c < 2; c++)
        #pragma unroll
        for (int i = 0; i < 4; i++) acc[c][i] = 0.f;

    // prologue: stages 0,1
    #pragma unroll
    for (int p = 0; p < NSTAGE-1; p++) {
        fill_async(sm + p*STGSZ, t, b, row0, p*BK);
        asm volatile("cp.async.commit_group;" ::: "memory");
    }

    for (int kt = 0; kt < NT; kt++) {
        asm volatile("cp.async.wait_group 1;" ::: "memory");
        __syncthreads();
        if (kt + NSTAGE - 1 < NT)
            fill_async(sm + ((kt + NSTAGE - 1) % NSTAGE)*STGSZ, t, b, row0, (kt + NSTAGE - 1)*BK);
        asm volatile("cp.async.commit_group;" ::: "memory");

        char* base = sm + (kt % NSTAGE)*STGSZ;
        #pragma unroll
        for (int kk = 0; kk < 4; kk++) {
            int kb = kk * 32;
            int xa0 = (t4*4 + kb) ^ (g << 4);
            int xa1 = (t4*4 + kb + 16) ^ (g << 4);
            uint32_t ah[4], al[4];
            int arow = (wm*16 + g) * 128;
            ah[0] = *(uint32_t*)(base + AHI_OFF + arow + xa0);
            ah[1] = *(uint32_t*)(base + AHI_OFF + arow + 1024 + xa0);
            ah[2] = *(uint32_t*)(base + AHI_OFF + arow + xa1);
            ah[3] = *(uint32_t*)(base + AHI_OFF + arow + 1024 + xa1);
            al[0] = *(uint32_t*)(base + ALO_OFF + arow + xa0);
            al[1] = *(uint32_t*)(base + ALO_OFF + arow + 1024 + xa0);
            al[2] = *(uint32_t*)(base + ALO_OFF + arow + xa1);
            al[3] = *(uint32_t*)(base + ALO_OFF + arow + 1024 + xa1);
            #pragma unroll
            for (int c = 0; c < 2; c++) {
                int brow = (wn*16 + c*8 + g) * 128;
                uint32_t bh[2], bl[2];
                bh[0] = *(uint32_t*)(base + BHI_OFF + brow + xa0);
                bh[1] = *(uint32_t*)(base + BHI_OFF + brow + xa1);
                bl[0] = *(uint32_t*)(base + BLO_OFF + brow + xa0);
                bl[1] = *(uint32_t*)(base + BLO_OFF + brow + xa1);
                mma16816(acc[c], ah, bh);
                mma16816(acc[c], ah, bl);
                mma16816(acc[c], al, bh);
            }
        }
        __syncthreads();
    }

    // ---- epilogue: self-loop + dm + bias + relu ----
    int rowL = row0 + wm*16 + g;
    int rowH = rowL + 8;
    float dmL = g_dm[b*N_ + rowL], adL = g_add[b*N_ + rowL];
    float dmH = g_dm[b*N_ + rowH], adH = g_add[b*N_ + rowH];
    const float* Yg = g_Y + (size_t)b*N_*HID_;
    float* Hg = g_H + (size_t)b*N_*HID_;
    #pragma unroll
    for (int c = 0; c < 2; c++) {
        int col = wn*16 + c*8 + 2*t4;
        float2 bs = *(const float2*)&bias[col];
        float2 yL = *(const float2*)&Yg[(size_t)rowL*HID_ + col];
        float2 yH = *(const float2*)&Yg[(size_t)rowH*HID_ + col];
        float2 o;
        o.x = fmaxf(fmaf(dmL, acc[c][0] + adL*yL.x, bs.x), 0.f);
        o.y = fmaxf(fmaf(dmL, acc[c][1] + adL*yL.y, bs.y), 0.f);
        *(float2*)&Hg[(size_t)rowL*HID_ + col] = o;
        o.x = fmaxf(fmaf(dmH, acc[c][2] + adH*yH.x, bs.x), 0.f);
        o.y = fmaxf(fmaf(dmH, acc[c][3] + adH*yH.y, bs.y), 0.f);
        *(float2*)&Hg[(size_t)rowH*HID_ + col] = o;
    }
}

// ---------------- global max pool ----------------
__global__ void pool_kernel() {
    int b = blockIdx.x, t = threadIdx.x;
    int f = t & 31, g = t >> 5;
    float m = -1e30f;
    for (int n = g; n < N_; n += 8)
        m = fmaxf(m, g_H[((size_t)b*N_ + n)*HID_ + f]);
    __shared__ float red[256];
    red[t] = m; __syncthreads();
    if (t < 128) red[t] = fmaxf(red[t], red[t+128]); __syncthreads();
    if (t < 64)  red[t] = fmaxf(red[t], red[t+64]);  __syncthreads();
    if (t < 32)  g_pool[b*HID_ + t] = fmaxf(red[t], red[t+32]);
}

// ---------------- MLP head ----------------
__global__ void head_kernel(const float* __restrict__ Wf1, const float* __restrict__ bf1,
                            const float* __restrict__ Wf2, const float* __restrict__ bf2,
                            float* __restrict__ out) {
    int w = threadIdx.x >> 5, lane = threadIdx.x & 31;
    float o = 0.f;
    #pragma unroll
    for (int ii = 0; ii < 2; ii++) {
        int j = lane + 32*ii;
        float s = bf1[j];
        #pragma unroll
        for (int f = 0; f < HID_; f++) s += g_pool[w*HID_ + f] * Wf1[f*2*HID_ + j];
        o += fmaxf(s, 0.f) * Wf2[j];
    }
    #pragma unroll
    for (int off = 16; off; off >>= 1) o += __shfl_xor_sync(0xffffffffu, o, off);
    if (lane == 0) out[w] = o + bf2[0];
}

// ---------------- launch ----------------
extern "C" void kernel_launch(void* const* d_in, const int* in_sizes, int n_in,
                              void* d_out, int out_size) {
    const float* x   = (const float*)d_in[0];
    const float* a   = (const float*)d_in[1];
    const float* W1  = (const float*)d_in[2];
    const float* b1  = (const float*)d_in[3];
    const float* W2  = (const float*)d_in[4];
    const float* b2  = (const float*)d_in[5];
    const float* W3  = (const float*)d_in[6];
    const float* b3  = (const float*)d_in[7];
    const float* Wf1 = (const float*)d_in[8];
    const float* bf1 = (const float*)d_in[9];
    const float* Wf2 = (const float*)d_in[10];
    const float* bf2 = (const float*)d_in[11];
    float* out = (float*)d_out;

    static int inited = 0;
    if (!inited) {
        cudaFuncSetAttribute(gemm_kernel, cudaFuncAttributeMaxDynamicSharedMemorySize, GEMM_SMEM);
        inited = 1;
    }

    dim3 gg(N_/BM, B_);

    deg_cvt_kernel<<<BN_TOTAL/8, 256>>>(a);

    y_kernel<F_><<<BN_TOTAL/32, 256>>>(x, W1);
    gemm_kernel<<<gg, 256, GEMM_SMEM>>>(b1);

    y_kernel<HID_><<<BN_TOTAL/32, 256>>>(nullptr, W2);
    gemm_kernel<<<gg, 256, GEMM_SMEM>>>(b2);

    y_kernel<HID_><<<BN_TOTAL/32, 256>>>(nullptr, W3);
    gemm_kernel<<<gg, 256, GEMM_SMEM>>>(b3);

    pool_kernel<<<B_, 256>>>();
    head_kernel<<<1, 256>>>(Wf1, bf1, Wf2, bf2, out);
}